// round 1
// baseline (speedup 1.0000x reference)
#include <cuda_runtime.h>
#include <cuda_bf16.h>

// Problem constants (fixed shapes from setup_inputs)
#define B_DIM 8
#define T_DIM 4096
#define D_DIM 1024
#define K_FFT 64
#define F_DIM (K_FFT / 2 + 1)   // 33

// Scratch: per-channel time-domain filter (irfft of sigmoid(mask)), mix_w folded in.
__device__ float g_filt[D_DIM * K_FFT];

// ---------------------------------------------------------------------------
// Kernel 1: build filters.  filt[d][n] = mix_w[d] * (1/64) *
//   ( g[0] + 2*sum_{f=1..31} g[f]*cos(2*pi*f*n/64) + g[32]*(-1)^n ),
// g = sigmoid(mask[d][:]).  Uses an exact 64-entry cos table via cospif.
// ---------------------------------------------------------------------------
__global__ void __launch_bounds__(64) spectral_filt_kernel(
    const float* __restrict__ mask, const float* __restrict__ mix_w,
    float* __restrict__ filt)
{
    __shared__ float g[F_DIM];
    __shared__ float tab[K_FFT];

    const int d = blockIdx.x;
    const int n = threadIdx.x;

    if (n < F_DIM) {
        float m = mask[d * F_DIM + n];
        g[n] = 1.0f / (1.0f + expf(-m));
    }
    // cos(2*pi*n/64) = cospi(n/32)
    tab[n] = cospif((float)n * (1.0f / 32.0f));
    __syncthreads();

    float s = g[0] + g[F_DIM - 1] * tab[(32 * n) & 63];
    #pragma unroll
    for (int f = 1; f < F_DIM - 1; f++) {
        s += 2.0f * g[f] * tab[(f * n) & 63];
    }
    filt[d * K_FFT + n] = s * (1.0f / 64.0f) * mix_w[d];
}

// ---------------------------------------------------------------------------
// Kernel 2: zero the whole output (vectorized, grid-stride).
// ---------------------------------------------------------------------------
__global__ void __launch_bounds__(256) spectral_zero_kernel(
    float4* __restrict__ out, long long n4)
{
    long long i = (long long)blockIdx.x * blockDim.x + threadIdx.x;
    long long stride = (long long)gridDim.x * blockDim.x;
    const float4 z = make_float4(0.f, 0.f, 0.f, 0.f);
    for (; i < n4; i += stride) out[i] = z;
}

// ---------------------------------------------------------------------------
// Kernel 3: circular convolution of the last-64 window with per-channel filter.
// Grid: (D/64, B).  Block: 256 threads = 4 t-groups x 64 channels.
// Each thread owns one channel (dl) and 16 consecutive output timesteps.
// Filter row is pre-rotated into registers so the 64x16 FMA loop has
// compile-time register indices (no shared traffic in the hot loop).
// ---------------------------------------------------------------------------
__global__ void __launch_bounds__(256) spectral_conv_kernel(
    const float* __restrict__ x, const float* __restrict__ filt,
    float* __restrict__ out)
{
    __shared__ float w_sh[K_FFT * 64];      // [k][dl], dl contiguous
    __shared__ float f_sh[64 * (K_FFT + 1)]; // [dl][n], padded stride 65

    const int b  = blockIdx.y;
    const int d0 = blockIdx.x * 64;
    const int tid = threadIdx.x;

    // Stage window rows T-64..T-1 for channels d0..d0+63 (coalesced).
    const float* xb = x + ((long long)b * T_DIM + (T_DIM - K_FFT)) * D_DIM + d0;
    #pragma unroll
    for (int i = 0; i < 16; i++) {
        int idx = tid + i * 256;
        int k = idx >> 6, dl = idx & 63;
        w_sh[idx] = xb[(long long)k * D_DIM + dl];
    }
    // Stage filter tile (coalesced: n contiguous in global).
    #pragma unroll
    for (int i = 0; i < 16; i++) {
        int idx = tid + i * 256;
        int dl = idx >> 6, n = idx & 63;
        f_sh[dl * 65 + n] = filt[(d0 + dl) * K_FFT + n];
    }
    __syncthreads();

    const int dl = tid & 63;
    const int tg = tid >> 6;      // 0..3
    const int t0 = tg * 16;

    // Pre-rotated filter: fr[i] = f[(t0 + i) & 63]  -> y[t0+j] = sum_k w[k]*fr[(j-k)&63]
    float fr[K_FFT];
    #pragma unroll
    for (int i = 0; i < K_FFT; i++)
        fr[i] = f_sh[dl * 65 + ((t0 + i) & 63)];

    float acc[16];
    #pragma unroll
    for (int j = 0; j < 16; j++) acc[j] = 0.0f;

    #pragma unroll
    for (int k = 0; k < K_FFT; k++) {
        float wv = w_sh[k * 64 + dl];
        #pragma unroll
        for (int j = 0; j < 16; j++)
            acc[j] += wv * fr[(j - k + K_FFT) & 63];   // compile-time index
    }

    float* ob = out + ((long long)b * T_DIM + (T_DIM - K_FFT)) * D_DIM + d0;
    #pragma unroll
    for (int j = 0; j < 16; j++)
        ob[(long long)(t0 + j) * D_DIM + dl] = acc[j];
}

// ---------------------------------------------------------------------------
// Launch
// ---------------------------------------------------------------------------
extern "C" void kernel_launch(void* const* d_in, const int* in_sizes, int n_in,
                              void* d_out, int out_size)
{
    const float* x     = (const float*)d_in[0];   // (B, T, D) fp32
    const float* mask  = (const float*)d_in[1];   // (D, 33)   fp32
    const float* mix_w = (const float*)d_in[2];   // (D,)      fp32
    float* out = (float*)d_out;                   // (B, T, D) fp32

    float* filt;
    cudaGetSymbolAddress((void**)&filt, g_filt);

    // 1) Build per-channel filters.
    spectral_filt_kernel<<<D_DIM, 64>>>(mask, mix_w, filt);

    // 2) Zero the full output.
    long long n4 = (long long)out_size / 4;
    spectral_zero_kernel<<<2368, 256>>>((float4*)out, n4);

    // 3) Compute the last-64-timestep window via circular convolution.
    dim3 grid(D_DIM / 64, B_DIM);
    spectral_conv_kernel<<<grid, 256>>>(x, filt, out);
}

// round 2
// speedup vs baseline: 1.0010x; 1.0010x over previous
#include <cuda_runtime.h>
#include <cuda_bf16.h>

// Problem constants (fixed shapes from setup_inputs)
#define B_DIM 8
#define T_DIM 4096
#define D_DIM 1024
#define K_FFT 64
#define F_DIM (K_FFT / 2 + 1)        // 33

#define CONV_BLOCKS (B_DIM * (D_DIM / 64))   // 128
#define GRID_TOTAL  740                      // one wave @ 5 blocks/SM (smem-limited)

// ---------------------------------------------------------------------------
// Fused kernel:
//   blocks [0, CONV_BLOCKS): per-(batch, 64-channel tile) filter build +
//       circular convolution of the last K_FFT timesteps.
//   blocks [CONV_BLOCKS, grid): grid-stride zero-fill of rows [0, T-K) for
//       every batch (disjoint region from the conv writes).
// ---------------------------------------------------------------------------
__global__ void __launch_bounds__(256) spectral_fused_kernel(
    const float* __restrict__ x, const float* __restrict__ mask,
    const float* __restrict__ mix_w, float* __restrict__ out)
{
    __shared__ float g_sh[64 * F_DIM];        // sigmoid(mask) tile [dl][f]
    __shared__ float tab[K_FFT];              // cos(2*pi*n/64)
    __shared__ float w_sh[K_FFT * 64];        // window [k][dl]
    __shared__ float f_sh[64 * (K_FFT + 1)];  // filter [dl][n], pad 65

    const int bid = blockIdx.x;
    const int tid = threadIdx.x;

    if (bid >= CONV_BLOCKS) {
        // ---- zero path: fill rows [0, T-K) of each batch with zeros ----
        const long long z4_per_b = (long long)(T_DIM - K_FFT) * D_DIM / 4; // 1032192
        const long long n4       = z4_per_b * B_DIM;
        const long long b_stride4 = (long long)T_DIM * D_DIM / 4;
        float4* __restrict__ o4 = (float4*)out;
        const float4 z = make_float4(0.f, 0.f, 0.f, 0.f);

        long long i = (long long)(bid - CONV_BLOCKS) * 256 + tid;
        const long long stride = (long long)(gridDim.x - CONV_BLOCKS) * 256;
        for (; i < n4; i += stride) {
            long long b   = i / z4_per_b;             // const-div -> mul/shift
            long long off = i - b * z4_per_b;
            o4[b * b_stride4 + off] = z;
        }
        return;
    }

    // ---- conv path ----
    const int b  = bid >> 4;          // 0..7
    const int d0 = (bid & 15) * 64;   // channel tile base

    // Stage sigmoid(mask) for the 64 channels (2112 contiguous floats).
    const float* mrow = mask + (long long)d0 * F_DIM;
    for (int idx = tid; idx < 64 * F_DIM; idx += 256)
        g_sh[idx] = 1.0f / (1.0f + expf(-mrow[idx]));
    if (tid < K_FFT)
        tab[tid] = cospif((float)tid * (1.0f / 32.0f));   // exact twiddles

    // Stage the last-64-timestep window (coalesced).
    const float* xb = x + ((long long)b * T_DIM + (T_DIM - K_FFT)) * D_DIM + d0;
    #pragma unroll
    for (int i = 0; i < 16; i++) {
        int idx = tid + i * 256;
        int k = idx >> 6, dl = idx & 63;
        w_sh[idx] = xb[(long long)k * D_DIM + dl];
    }
    __syncthreads();

    // Build time-domain filter: f[dl][n] = mix_w/64 *
    //   ( g0 + 2*sum_{f=1..31} g_f cos(2 pi f n/64) + g32*(-1)^n )
    #pragma unroll
    for (int i = 0; i < 16; i++) {
        int idx = tid + i * 256;
        int dl = idx >> 6, n = idx & 63;
        const float* gd = g_sh + dl * F_DIM;
        float s = gd[0] + gd[32] * tab[(32 * n) & 63];
        #pragma unroll
        for (int f = 1; f < 32; f++)
            s += 2.0f * gd[f] * tab[(f * n) & 63];
        f_sh[dl * 65 + n] = s * (1.0f / 64.0f) * mix_w[d0 + dl];
    }
    __syncthreads();

    const int dl = tid & 63;
    const int tg = tid >> 6;       // 0..3
    const int t0 = tg * 16;

    // Pre-rotated filter in registers: fr[i] = f[(t0+i)&63]
    float fr[K_FFT];
    #pragma unroll
    for (int i = 0; i < K_FFT; i++)
        fr[i] = f_sh[dl * 65 + ((t0 + i) & 63)];

    float acc[16];
    #pragma unroll
    for (int j = 0; j < 16; j++) acc[j] = 0.0f;

    #pragma unroll
    for (int k = 0; k < K_FFT; k++) {
        float wv = w_sh[k * 64 + dl];
        #pragma unroll
        for (int j = 0; j < 16; j++)
            acc[j] += wv * fr[(j - k + K_FFT) & 63];   // compile-time reg index
    }

    float* ob = out + ((long long)b * T_DIM + (T_DIM - K_FFT)) * D_DIM + d0;
    #pragma unroll
    for (int j = 0; j < 16; j++)
        ob[(long long)(t0 + j) * D_DIM + dl] = acc[j];
}

// ---------------------------------------------------------------------------
// Launch: one kernel, one graph node.
// ---------------------------------------------------------------------------
extern "C" void kernel_launch(void* const* d_in, const int* in_sizes, int n_in,
                              void* d_out, int out_size)
{
    const float* x     = (const float*)d_in[0];   // (B, T, D) fp32
    const float* mask  = (const float*)d_in[1];   // (D, 33)   fp32
    const float* mix_w = (const float*)d_in[2];   // (D,)      fp32
    float* out = (float*)d_out;                   // (B, T, D) fp32

    spectral_fused_kernel<<<GRID_TOTAL, 256>>>(x, mask, mix_w, out);
}